// round 9
// baseline (speedup 1.0000x reference)
#include <cuda_runtime.h>
#include <math.h>

#define BB 16
#define LL 2048
#define MM 32000
#define DD 512
#define DV 128              // DD/4 float4 per row
#define SM_SCALE 0.03125f   // 1/sqrt(2*D) = 1/32
#define G_INNER 444
#define NCHUNK 128          // m-chunks for weighted sum
#define CHUNK_M (LL / NCHUNK)   // 16

// ---------------- scratch (no allocations allowed) ----------------
__device__ __align__(16) float g_inv_ew[MM + 1];
__device__ __align__(16) float g_dotM[MM + 1];     // ew[j]·ew[M] raw
__device__ __align__(16) float g_inv_pw[LL];
__device__ __align__(16) float g_pwdot[BB * LL];   // pw[q_b]·pw[m] raw
__device__ __align__(16) float g_sel_partial[BB * NCHUNK * DD];
__device__ __align__(16) float g_denom_partial[BB * NCHUNK];
__device__ __align__(16) float g_sel[BB * DD];
__device__ __align__(16) float g_lse_partial[G_INNER * BB * 2];

__device__ __forceinline__ float warp_sum(float v) {
#pragma unroll
    for (int o = 16; o; o >>= 1) v += __shfl_xor_sync(0xffffffffu, v, o);
    return v;
}

// ---------------- 1) ew pass: inverse norm + dot with ew[M] -----------------
__global__ void __launch_bounds__(256) ew_pass_kernel(const float* __restrict__ ew) {
    __shared__ float4 s_eM[DV];
    int tid = threadIdx.x;
    const float4* eMg = (const float4*)(ew + (size_t)MM * DD);
    if (tid < DV) s_eM[tid] = __ldg(&eMg[tid]);
    __syncthreads();
    int w = (blockIdx.x * 256 + tid) >> 5;
    int lane = tid & 31;
    if (w > MM) return;
    const float4* src = (const float4*)(ew + (size_t)w * DD);
    float s = 0.f, d = 0.f;
#pragma unroll
    for (int k = 0; k < 4; k++) {
        float4 v = __ldg(&src[lane + 32 * k]);
        float4 e = s_eM[lane + 32 * k];
        s += v.x * v.x + v.y * v.y + v.z * v.z + v.w * v.w;
        d += v.x * e.x + v.y * e.y + v.z * e.z + v.w * e.w;
    }
#pragma unroll
    for (int o = 16; o; o >>= 1) {
        s += __shfl_xor_sync(0xffffffffu, s, o);
        d += __shfl_xor_sync(0xffffffffu, d, o);
    }
    if (lane == 0) {
        g_inv_ew[w] = 1.0f / fmaxf(sqrtf(s), 1.0f);
        g_dotM[w] = d;
    }
}

// ---------------- 2) pw pass: q-rows staged in smem ------------------------
__global__ void __launch_bounds__(256) pw_pass_kernel(const float* __restrict__ pw,
                                                      const int* __restrict__ mask_idx) {
    __shared__ float4 s_q[BB * DV];   // 32 KB: the 16 selected q rows
    int tid = threadIdx.x;
#pragma unroll
    for (int i = 0; i < 8; i++) {
        int idx = tid + i * 256;            // [row*DV + col]
        int row = idx >> 7;
        int col = idx & 127;
        int q = __ldg(&mask_idx[row]);
        s_q[idx] = __ldg((const float4*)(pw + (size_t)q * DD) + col);
    }
    __syncthreads();

    int w = (blockIdx.x * 256 + tid) >> 5;  // row m, 0..2047 (exact)
    int lane = tid & 31;
    const float4* src = (const float4*)(pw + (size_t)w * DD);
    float4 r4[4];
    float s = 0.f;
#pragma unroll
    for (int k = 0; k < 4; k++) {
        r4[k] = __ldg(&src[lane + 32 * k]);
        s += r4[k].x * r4[k].x + r4[k].y * r4[k].y + r4[k].z * r4[k].z + r4[k].w * r4[k].w;
    }
    float dotv[BB];
#pragma unroll
    for (int b = 0; b < BB; b++) {
        float d = 0.f;
#pragma unroll
        for (int k = 0; k < 4; k++) {
            float4 e = s_q[b * DV + lane + 32 * k];
            d += r4[k].x * e.x + r4[k].y * e.y + r4[k].z * e.z + r4[k].w * e.w;
        }
        dotv[b] = d;
    }
    s = warp_sum(s);
#pragma unroll
    for (int b = 0; b < BB; b++) dotv[b] = warp_sum(dotv[b]);
    if (lane == 0) g_inv_pw[w] = 1.0f / fmaxf(sqrtf(s), 1.0f);
    if (lane < BB) g_pwdot[lane * LL + w] = dotv[lane];
}

// ---------------- 3) fused weights + gather: unnormalized softmax ----------
__global__ void __launch_bounds__(128) wsum_kernel(const int* __restrict__ x,
                                                   const int* __restrict__ mask_idx,
                                                   const float* __restrict__ ew) {
    int chunk = blockIdx.x, b = blockIdx.y, t = threadIdx.x;
    __shared__ float psc[CHUNK_M];
    __shared__ int rows[CHUNK_M];
    if (t < 32) {
        float wgt = 0.f;
        if (t < CHUNK_M) {
            int m = chunk * CHUNK_M + t;
            int q = __ldg(&mask_idx[b]);
            int xin = (m == q) ? MM : __ldg(&x[b * LL + m]);
            float invM = g_inv_ew[MM];
            float invq = g_inv_pw[q];
            float lg = (g_dotM[xin] * invM * g_inv_ew[xin]
                      + g_pwdot[b * LL + m] * invq * g_inv_pw[m]) * SM_SCALE;
            wgt = __expf(lg);
            rows[t] = xin;
            psc[t] = wgt * g_inv_ew[xin];
        }
        float dsum = warp_sum(wgt);
        if (t == 0) g_denom_partial[b * NCHUNK + chunk] = dsum;
    }
    __syncthreads();
    float4 acc = make_float4(0.f, 0.f, 0.f, 0.f);
#pragma unroll
    for (int i = 0; i < CHUNK_M; i++) {
        float p = psc[i];
        float4 v = __ldg((const float4*)(ew + (size_t)rows[i] * DD) + t);
        acc.x += p * v.x; acc.y += p * v.y; acc.z += p * v.z; acc.w += p * v.w;
    }
    ((float4*)g_sel_partial)[((size_t)b * NCHUNK + chunk) * DV + t] = acc;
}

// ---------------- 4) reduce partials + normalize (R5-proven form) -----------
__global__ void __launch_bounds__(256) reduce_sel_kernel(float* out_sel) {
    int cg = blockIdx.x;
    int b = blockIdx.y;
    int t = threadIdx.x;
    int col = cg * 16 + (t & 15);
    int part = t >> 4;                  // 0..15
    __shared__ float4 sh[256];
    __shared__ float sh_d[8];
    __shared__ float s_invd;

    float4 acc = make_float4(0.f, 0.f, 0.f, 0.f);
#pragma unroll
    for (int c = part * 8; c < part * 8 + 8; c++) {
        float4 v = ((const float4*)g_sel_partial)[((size_t)b * NCHUNK + c) * DV + col];
        acc.x += v.x; acc.y += v.y; acc.z += v.z; acc.w += v.w;
    }
    sh[t] = acc;

    float d = (t < NCHUNK) ? g_denom_partial[b * NCHUNK + t] : 0.f;
    d = warp_sum(d);
    if ((t & 31) == 0) sh_d[t >> 5] = d;
    __syncthreads();
    if (t == 0) {
        float dd = 0.f;
#pragma unroll
        for (int i = 0; i < 8; i++) dd += sh_d[i];
        s_invd = 1.0f / dd;
    }
    __syncthreads();

    if (t < 16) {
        float4 a = sh[t];
#pragma unroll
        for (int p = 1; p < 16; p++) {
            float4 v = sh[p * 16 + t];
            a.x += v.x; a.y += v.y; a.z += v.z; a.w += v.w;
        }
        float inv = s_invd;
        a.x *= inv; a.y *= inv; a.z *= inv; a.w *= inv;
        int c = cg * 16 + t;
        ((float4*)g_sel)[b * DV + c] = a;
        if (out_sel) {
            float* o = out_sel + b * DD + c * 4;
            o[0] = a.x; o[1] = a.y; o[2] = a.z; o[3] = a.w;
        }
    }
}

// ---------------- 5) inner v2: 2 rows/group, scalar FMA, low regs -----------
// lane j permanently owns batch j>>1; rows row0+(j&1). acc index = b*2 + r.
__global__ void __launch_bounds__(256) inner_kernel(const float* __restrict__ ew) {
    __shared__ float4 sel_sh[BB * DV];    // 32 KB
    __shared__ float sh_m[8][16];
    __shared__ float sh_s[8][16];
    int tid = threadIdx.x;
    const float4* gsel = (const float4*)g_sel;
#pragma unroll
    for (int i = 0; i < 8; i++) sel_sh[tid + i * 256] = gsel[tid + i * 256];
    __syncthreads();

    int warp = tid >> 5, lane = tid & 31;
    int wg = blockIdx.x * 8 + warp;
    const int W = G_INNER * 8;

    float mm = -1e30f, ss = 0.f;       // online lse for batch lane>>1

    for (int g = wg; g < (MM / 2); g += W) {
        int row0 = g * 2;
        float4 e0[4], e1[4];
        const float4* rp0 = (const float4*)(ew + (size_t)row0 * DD);
        const float4* rp1 = (const float4*)(ew + (size_t)(row0 + 1) * DD);
#pragma unroll
        for (int v = 0; v < 4; v++) {
            e0[v] = __ldg(&rp0[lane + 32 * v]);
            e1[v] = __ldg(&rp1[lane + 32 * v]);
        }
        float myinv = __ldg(&g_inv_ew[row0 + (lane & 1)]);

        float acc[32];
#pragma unroll
        for (int bl = 0; bl < 16; bl++) {
            float a0 = 0.f, a1 = 0.f;
#pragma unroll
            for (int v = 0; v < 4; v++) {
                float4 s4 = sel_sh[bl * DV + lane + 32 * v];
                a0 += e0[v].x * s4.x + e0[v].y * s4.y + e0[v].z * s4.z + e0[v].w * s4.w;
                a1 += e1[v].x * s4.x + e1[v].y * s4.y + e1[v].z * s4.z + e1[v].w * s4.w;
            }
            acc[bl * 2 + 0] = a0;
            acc[bl * 2 + 1] = a1;
        }
        // register-exchange tree reduce: lane j ends with total for index j
#pragma unroll
        for (int i = 0; i < 16; i++) {
            float lo = acc[i], hi = acc[i + 16];
            float send = (lane & 16) ? lo : hi;
            float recv = __shfl_xor_sync(0xffffffffu, send, 16);
            acc[i] = ((lane & 16) ? hi : lo) + recv;
        }
#pragma unroll
        for (int i = 0; i < 8; i++) {
            float lo = acc[i], hi = acc[i + 8];
            float send = (lane & 8) ? lo : hi;
            float recv = __shfl_xor_sync(0xffffffffu, send, 8);
            acc[i] = ((lane & 8) ? hi : lo) + recv;
        }
#pragma unroll
        for (int i = 0; i < 4; i++) {
            float lo = acc[i], hi = acc[i + 4];
            float send = (lane & 4) ? lo : hi;
            float recv = __shfl_xor_sync(0xffffffffu, send, 4);
            acc[i] = ((lane & 4) ? hi : lo) + recv;
        }
#pragma unroll
        for (int i = 0; i < 2; i++) {
            float lo = acc[i], hi = acc[i + 2];
            float send = (lane & 2) ? lo : hi;
            float recv = __shfl_xor_sync(0xffffffffu, send, 2);
            acc[i] = ((lane & 2) ? hi : lo) + recv;
        }
        {
            float lo = acc[0], hi = acc[1];
            float send = (lane & 1) ? lo : hi;
            float recv = __shfl_xor_sync(0xffffffffu, send, 1);
            acc[0] = ((lane & 1) ? hi : lo) + recv;
        }
        float val = acc[0] * myinv;   // (b = lane>>1, row = row0 + (lane&1))
        if (val > mm) { ss = ss * __expf(mm - val) + 1.0f; mm = val; }
        else          { ss += __expf(val - mm); }
    }
    // merge the 2 lanes that share a batch
    {
        float m2 = __shfl_xor_sync(0xffffffffu, mm, 1);
        float s2 = __shfl_xor_sync(0xffffffffu, ss, 1);
        float mn = fmaxf(mm, m2);
        ss = ss * __expf(mm - mn) + s2 * __expf(m2 - mn);
        mm = mn;
    }
    if ((lane & 1) == 0) {
        sh_m[warp][lane >> 1] = mm;
        sh_s[warp][lane >> 1] = ss;
    }
    __syncthreads();
    if (tid < 16) {
        float m = -1e30f, s = 0.f;
#pragma unroll
        for (int w2 = 0; w2 < 8; w2++) {
            float m2 = sh_m[w2][tid], s2 = sh_s[w2][tid];
            float mn = fmaxf(m, m2);
            s = s * __expf(m - mn) + s2 * __expf(m2 - mn);
            m = mn;
        }
        g_lse_partial[(blockIdx.x * 16 + tid) * 2 + 0] = m;
        g_lse_partial[(blockIdx.x * 16 + tid) * 2 + 1] = s;
    }
}

// ---------------- 6) finalize: lse merge + target dot + loss ----------------
__global__ void __launch_bounds__(512) finalize_kernel(const int* __restrict__ x,
                                                       const int* __restrict__ mask_idx,
                                                       const float* __restrict__ ew,
                                                       float* out_loss) {
    __shared__ float contrib[BB];
    int warp = threadIdx.x >> 5, lane = threadIdx.x & 31;
    int b = warp;
    float m = -1e30f, s = 0.f;
    for (int i = lane; i < G_INNER; i += 32) {
        float m2 = g_lse_partial[(i * 16 + b) * 2 + 0];
        float s2 = g_lse_partial[(i * 16 + b) * 2 + 1];
        float mn = fmaxf(m, m2);
        s = s * __expf(m - mn) + s2 * __expf(m2 - mn);
        m = mn;
    }
#pragma unroll
    for (int o = 16; o; o >>= 1) {
        float m2 = __shfl_xor_sync(0xffffffffu, m, o);
        float s2 = __shfl_xor_sync(0xffffffffu, s, o);
        float mn = fmaxf(m, m2);
        s = s * __expf(m - mn) + s2 * __expf(m2 - mn);
        m = mn;
    }
    int q = __ldg(&mask_idx[b]);
    int t = __ldg(&x[b * LL + q]);
    const float4* tr = (const float4*)(ew + (size_t)t * DD);
    const float4* sv = (const float4*)(g_sel + (size_t)b * DD);
    float dp = 0.f;
#pragma unroll
    for (int v = 0; v < 4; v++) {
        float4 a = __ldg(&tr[lane + 32 * v]);
        float4 c = sv[lane + 32 * v];
        dp += a.x * c.x + a.y * c.y + a.z * c.z + a.w * c.w;
    }
    dp = warp_sum(dp);
    if (lane == 0) contrib[b] = dp * g_inv_ew[t] - (m + logf(s));
    __syncthreads();
    if (threadIdx.x == 0 && out_loss) {
        float acc = 0.f;
#pragma unroll
        for (int b2 = 0; b2 < BB; b2++) acc += contrib[b2];
        *out_loss = -acc * (1.0f / BB);
    }
}

// ---------------- launch -----------------------------------------------------
extern "C" void kernel_launch(void* const* d_in, const int* in_sizes, int n_in,
                              void* d_out, int out_size) {
    const int* x = (const int*)d_in[0];
    const int* mask_idx = (const int*)d_in[1];
    const float* ew = (const float*)d_in[2];
    const float* pw = (const float*)d_in[3];
    float* out = (float*)d_out;

    float* out_loss;
    float* out_sel;
    if (out_size == BB * DD) { out_sel = out; out_loss = nullptr; }
    else if (out_size == 1)  { out_sel = nullptr; out_loss = out; }
    else                     { out_loss = out; out_sel = out + 1; }

    ew_pass_kernel<<<(MM + 1 + 7) / 8, 256>>>(ew);
    pw_pass_kernel<<<LL / 8, 256>>>(pw, mask_idx);
    wsum_kernel<<<dim3(NCHUNK, BB), 128>>>(x, mask_idx, ew);
    reduce_sel_kernel<<<dim3(8, BB), 256>>>(out_sel);
    inner_kernel<<<G_INNER, 256>>>(ew);
    finalize_kernel<<<1, 512>>>(x, mask_idx, ew, out_loss);
}

// round 10
// speedup vs baseline: 1.1479x; 1.1479x over previous
#include <cuda_runtime.h>
#include <math.h>

#define BB 16
#define LL 2048
#define MM 32000
#define DD 512
#define DV 128              // DD/4 float4 per row
#define SM_SCALE 0.03125f   // 1/sqrt(2*D) = 1/32
#define G_INNER 296
#define NCHUNK 128          // m-chunks for weighted sum
#define CHUNK_M (LL / NCHUNK)   // 16

// ---------------- scratch (no allocations allowed) ----------------
__device__ __align__(16) float g_inv_ew[MM + 1];
__device__ __align__(16) float g_dotM[MM + 1];     // ew[j]·ew[M] raw
__device__ __align__(16) float g_inv_pw[LL];
__device__ __align__(16) float g_pwdot[BB * LL];   // pw[q_b]·pw[m] raw
__device__ __align__(16) float g_sel_partial[BB * NCHUNK * DD];
__device__ __align__(16) float g_denom_partial[BB * NCHUNK];
__device__ __align__(16) float g_sel[BB * DD];
__device__ __align__(16) float g_lse_partial[G_INNER * BB * 2];

__device__ __forceinline__ float warp_sum(float v) {
#pragma unroll
    for (int o = 16; o; o >>= 1) v += __shfl_xor_sync(0xffffffffu, v, o);
    return v;
}

// ---------------- 1) ew pass: inverse norm + dot with ew[M] -----------------
__global__ void __launch_bounds__(256) ew_pass_kernel(const float* __restrict__ ew) {
    __shared__ float4 s_eM[DV];
    int tid = threadIdx.x;
    const float4* eMg = (const float4*)(ew + (size_t)MM * DD);
    if (tid < DV) s_eM[tid] = __ldg(&eMg[tid]);
    __syncthreads();
    int w = (blockIdx.x * 256 + tid) >> 5;
    int lane = tid & 31;
    if (w > MM) return;
    const float4* src = (const float4*)(ew + (size_t)w * DD);
    float s = 0.f, d = 0.f;
#pragma unroll
    for (int k = 0; k < 4; k++) {
        float4 v = __ldg(&src[lane + 32 * k]);
        float4 e = s_eM[lane + 32 * k];
        s += v.x * v.x + v.y * v.y + v.z * v.z + v.w * v.w;
        d += v.x * e.x + v.y * e.y + v.z * e.z + v.w * e.w;
    }
#pragma unroll
    for (int o = 16; o; o >>= 1) {
        s += __shfl_xor_sync(0xffffffffu, s, o);
        d += __shfl_xor_sync(0xffffffffu, d, o);
    }
    if (lane == 0) {
        g_inv_ew[w] = 1.0f / fmaxf(sqrtf(s), 1.0f);
        g_dotM[w] = d;
    }
}

// ---------------- 2) pw pass: q-rows staged in smem ------------------------
__global__ void __launch_bounds__(256) pw_pass_kernel(const float* __restrict__ pw,
                                                      const int* __restrict__ mask_idx) {
    __shared__ float4 s_q[BB * DV];   // 32 KB: the 16 selected q rows
    int tid = threadIdx.x;
#pragma unroll
    for (int i = 0; i < 8; i++) {
        int idx = tid + i * 256;            // [row*DV + col]
        int row = idx >> 7;
        int col = idx & 127;
        int q = __ldg(&mask_idx[row]);
        s_q[idx] = __ldg((const float4*)(pw + (size_t)q * DD) + col);
    }
    __syncthreads();

    int w = (blockIdx.x * 256 + tid) >> 5;  // row m, 0..2047 (exact)
    int lane = tid & 31;
    const float4* src = (const float4*)(pw + (size_t)w * DD);
    float4 r4[4];
    float s = 0.f;
#pragma unroll
    for (int k = 0; k < 4; k++) {
        r4[k] = __ldg(&src[lane + 32 * k]);
        s += r4[k].x * r4[k].x + r4[k].y * r4[k].y + r4[k].z * r4[k].z + r4[k].w * r4[k].w;
    }
    float dotv[BB];
#pragma unroll
    for (int b = 0; b < BB; b++) {
        float d = 0.f;
#pragma unroll
        for (int k = 0; k < 4; k++) {
            float4 e = s_q[b * DV + lane + 32 * k];
            d += r4[k].x * e.x + r4[k].y * e.y + r4[k].z * e.z + r4[k].w * e.w;
        }
        dotv[b] = d;
    }
    s = warp_sum(s);
#pragma unroll
    for (int b = 0; b < BB; b++) dotv[b] = warp_sum(dotv[b]);
    if (lane == 0) g_inv_pw[w] = 1.0f / fmaxf(sqrtf(s), 1.0f);
    if (lane < BB) g_pwdot[lane * LL + w] = dotv[lane];
}

// ---------------- 3) fused weights + gather: unnormalized softmax ----------
__global__ void __launch_bounds__(128) wsum_kernel(const int* __restrict__ x,
                                                   const int* __restrict__ mask_idx,
                                                   const float* __restrict__ ew) {
    int chunk = blockIdx.x, b = blockIdx.y, t = threadIdx.x;
    __shared__ float psc[CHUNK_M];
    __shared__ int rows[CHUNK_M];
    if (t < 32) {
        float wgt = 0.f;
        if (t < CHUNK_M) {
            int m = chunk * CHUNK_M + t;
            int q = __ldg(&mask_idx[b]);
            int xin = (m == q) ? MM : __ldg(&x[b * LL + m]);
            float invM = g_inv_ew[MM];
            float invq = g_inv_pw[q];
            float lg = (g_dotM[xin] * invM * g_inv_ew[xin]
                      + g_pwdot[b * LL + m] * invq * g_inv_pw[m]) * SM_SCALE;
            wgt = __expf(lg);
            rows[t] = xin;
            psc[t] = wgt * g_inv_ew[xin];
        }
        float dsum = warp_sum(wgt);
        if (t == 0) g_denom_partial[b * NCHUNK + chunk] = dsum;
    }
    __syncthreads();
    float4 acc = make_float4(0.f, 0.f, 0.f, 0.f);
#pragma unroll
    for (int i = 0; i < CHUNK_M; i++) {
        float p = psc[i];
        float4 v = __ldg((const float4*)(ew + (size_t)rows[i] * DD) + t);
        acc.x += p * v.x; acc.y += p * v.y; acc.z += p * v.z; acc.w += p * v.w;
    }
    ((float4*)g_sel_partial)[((size_t)b * NCHUNK + chunk) * DV + t] = acc;
}

// ---------------- 4) reduce partials + normalize (R5-proven form) -----------
__global__ void __launch_bounds__(256) reduce_sel_kernel(float* out_sel) {
    int cg = blockIdx.x;
    int b = blockIdx.y;
    int t = threadIdx.x;
    int col = cg * 16 + (t & 15);
    int part = t >> 4;                  // 0..15
    __shared__ float4 sh[256];
    __shared__ float sh_d[8];
    __shared__ float s_invd;

    float4 acc = make_float4(0.f, 0.f, 0.f, 0.f);
#pragma unroll
    for (int c = part * 8; c < part * 8 + 8; c++) {
        float4 v = ((const float4*)g_sel_partial)[((size_t)b * NCHUNK + c) * DV + col];
        acc.x += v.x; acc.y += v.y; acc.z += v.z; acc.w += v.w;
    }
    sh[t] = acc;

    float d = (t < NCHUNK) ? g_denom_partial[b * NCHUNK + t] : 0.f;
    d = warp_sum(d);
    if ((t & 31) == 0) sh_d[t >> 5] = d;
    __syncthreads();
    if (t == 0) {
        float dd = 0.f;
#pragma unroll
        for (int i = 0; i < 8; i++) dd += sh_d[i];
        s_invd = 1.0f / dd;
    }
    __syncthreads();

    if (t < 16) {
        float4 a = sh[t];
#pragma unroll
        for (int p = 1; p < 16; p++) {
            float4 v = sh[p * 16 + t];
            a.x += v.x; a.y += v.y; a.z += v.z; a.w += v.w;
        }
        float inv = s_invd;
        a.x *= inv; a.y *= inv; a.z *= inv; a.w *= inv;
        int c = cg * 16 + t;
        ((float4*)g_sel)[b * DV + c] = a;
        if (out_sel) {
            float* o = out_sel + b * DD + c * 4;
            o[0] = a.x; o[1] = a.y; o[2] = a.z; o[3] = a.w;
        }
    }
}

// ---------------- 5) inner v4: 4 rows/group, scalar FMA, transient ev -------
// acc[64]: index bl*4+r. Two 32-trees; lane j ends with batches j>>2 and 8+(j>>2),
// row row0+(j&3) — identical epilogue to the verified R5 kernel.
__global__ void __launch_bounds__(256, 2) inner_kernel(const float* __restrict__ ew) {
    __shared__ float4 sel_sh[BB * DV];    // 32 KB
    __shared__ float sh_m[8][16];
    __shared__ float sh_s[8][16];
    int tid = threadIdx.x;
    const float4* gsel = (const float4*)g_sel;
#pragma unroll
    for (int i = 0; i < 8; i++) sel_sh[tid + i * 256] = gsel[tid + i * 256];
    __syncthreads();

    int warp = tid >> 5, lane = tid & 31;
    int wg = blockIdx.x * 8 + warp;
    const int W = G_INNER * 8;

    float mA = -1e30f, sA = 0.f, mB = -1e30f, sB = 0.f;

    for (int g = wg; g < (MM / 4); g += W) {
        int row0 = g * 4;
        float myinv = __ldg(&g_inv_ew[row0 + (lane & 3)]);

        float acc[64];
#pragma unroll
        for (int k = 0; k < 64; k++) acc[k] = 0.f;

#pragma unroll
        for (int v = 0; v < 4; v++) {
            // ev fragments live only inside this v iteration (16 regs)
            float4 e0 = __ldg((const float4*)(ew + (size_t)(row0 + 0) * DD) + lane + 32 * v);
            float4 e1 = __ldg((const float4*)(ew + (size_t)(row0 + 1) * DD) + lane + 32 * v);
            float4 e2 = __ldg((const float4*)(ew + (size_t)(row0 + 2) * DD) + lane + 32 * v);
            float4 e3 = __ldg((const float4*)(ew + (size_t)(row0 + 3) * DD) + lane + 32 * v);
#pragma unroll
            for (int bl = 0; bl < 16; bl++) {
                float4 s4 = sel_sh[bl * DV + lane + 32 * v];
                acc[bl * 4 + 0] += e0.x * s4.x + e0.y * s4.y + e0.z * s4.z + e0.w * s4.w;
                acc[bl * 4 + 1] += e1.x * s4.x + e1.y * s4.y + e1.z * s4.z + e1.w * s4.w;
                acc[bl * 4 + 2] += e2.x * s4.x + e2.y * s4.y + e2.z * s4.z + e2.w * s4.w;
                acc[bl * 4 + 3] += e3.x * s4.x + e3.y * s4.y + e3.z * s4.z + e3.w * s4.w;
            }
        }

        // two register-exchange trees over acc[0..31] and acc[32..63]
#pragma unroll
        for (int half = 0; half < 2; half++) {
            float* a = acc + half * 32;
#pragma unroll
            for (int i = 0; i < 16; i++) {
                float lo = a[i], hi = a[i + 16];
                float send = (lane & 16) ? lo : hi;
                float recv = __shfl_xor_sync(0xffffffffu, send, 16);
                a[i] = ((lane & 16) ? hi : lo) + recv;
            }
#pragma unroll
            for (int i = 0; i < 8; i++) {
                float lo = a[i], hi = a[i + 8];
                float send = (lane & 8) ? lo : hi;
                float recv = __shfl_xor_sync(0xffffffffu, send, 8);
                a[i] = ((lane & 8) ? hi : lo) + recv;
            }
#pragma unroll
            for (int i = 0; i < 4; i++) {
                float lo = a[i], hi = a[i + 4];
                float send = (lane & 4) ? lo : hi;
                float recv = __shfl_xor_sync(0xffffffffu, send, 4);
                a[i] = ((lane & 4) ? hi : lo) + recv;
            }
#pragma unroll
            for (int i = 0; i < 2; i++) {
                float lo = a[i], hi = a[i + 2];
                float send = (lane & 2) ? lo : hi;
                float recv = __shfl_xor_sync(0xffffffffu, send, 2);
                a[i] = ((lane & 2) ? hi : lo) + recv;
            }
            {
                float lo = a[0], hi = a[1];
                float send = (lane & 1) ? lo : hi;
                float recv = __shfl_xor_sync(0xffffffffu, send, 1);
                a[0] = ((lane & 1) ? hi : lo) + recv;
            }
            float val = a[0] * myinv;  // batch half*8 + (lane>>2), row row0+(lane&3)
            if (half == 0) {
                if (val > mA) { sA = sA * __expf(mA - val) + 1.0f; mA = val; }
                else          { sA += __expf(val - mA); }
            } else {
                if (val > mB) { sB = sB * __expf(mB - val) + 1.0f; mB = val; }
                else          { sB += __expf(val - mB); }
            }
        }
    }
#pragma unroll
    for (int o = 1; o <= 2; o <<= 1) {
        float m2 = __shfl_xor_sync(0xffffffffu, mA, o);
        float s2 = __shfl_xor_sync(0xffffffffu, sA, o);
        float mn = fmaxf(mA, m2);
        sA = sA * __expf(mA - mn) + s2 * __expf(m2 - mn);
        mA = mn;
        m2 = __shfl_xor_sync(0xffffffffu, mB, o);
        s2 = __shfl_xor_sync(0xffffffffu, sB, o);
        mn = fmaxf(mB, m2);
        sB = sB * __expf(mB - mn) + s2 * __expf(m2 - mn);
        mB = mn;
    }
    if ((lane & 3) == 0) {
        int bA = lane >> 2;
        sh_m[warp][bA] = mA;     sh_s[warp][bA] = sA;
        sh_m[warp][8 + bA] = mB; sh_s[warp][8 + bA] = sB;
    }
    __syncthreads();
    if (tid < 16) {
        float m = -1e30f, s = 0.f;
#pragma unroll
        for (int w2 = 0; w2 < 8; w2++) {
            float m2 = sh_m[w2][tid], s2 = sh_s[w2][tid];
            float mn = fmaxf(m, m2);
            s = s * __expf(m - mn) + s2 * __expf(m2 - mn);
            m = mn;
        }
        g_lse_partial[(blockIdx.x * 16 + tid) * 2 + 0] = m;
        g_lse_partial[(blockIdx.x * 16 + tid) * 2 + 1] = s;
    }
}

// ---------------- 6) finalize: lse merge + target dot + loss ----------------
__global__ void __launch_bounds__(512) finalize_kernel(const int* __restrict__ x,
                                                       const int* __restrict__ mask_idx,
                                                       const float* __restrict__ ew,
                                                       float* out_loss) {
    __shared__ float contrib[BB];
    int warp = threadIdx.x >> 5, lane = threadIdx.x & 31;
    int b = warp;
    float m = -1e30f, s = 0.f;
    for (int i = lane; i < G_INNER; i += 32) {
        float m2 = g_lse_partial[(i * 16 + b) * 2 + 0];
        float s2 = g_lse_partial[(i * 16 + b) * 2 + 1];
        float mn = fmaxf(m, m2);
        s = s * __expf(m - mn) + s2 * __expf(m2 - mn);
        m = mn;
    }
#pragma unroll
    for (int o = 16; o; o >>= 1) {
        float m2 = __shfl_xor_sync(0xffffffffu, m, o);
        float s2 = __shfl_xor_sync(0xffffffffu, s, o);
        float mn = fmaxf(m, m2);
        s = s * __expf(m - mn) + s2 * __expf(m2 - mn);
        m = mn;
    }
    int q = __ldg(&mask_idx[b]);
    int t = __ldg(&x[b * LL + q]);
    const float4* tr = (const float4*)(ew + (size_t)t * DD);
    const float4* sv = (const float4*)(g_sel + (size_t)b * DD);
    float dp = 0.f;
#pragma unroll
    for (int v = 0; v < 4; v++) {
        float4 a = __ldg(&tr[lane + 32 * v]);
        float4 c = sv[lane + 32 * v];
        dp += a.x * c.x + a.y * c.y + a.z * c.z + a.w * c.w;
    }
    dp = warp_sum(dp);
    if (lane == 0) contrib[b] = dp * g_inv_ew[t] - (m + logf(s));
    __syncthreads();
    if (threadIdx.x == 0 && out_loss) {
        float acc = 0.f;
#pragma unroll
        for (int b2 = 0; b2 < BB; b2++) acc += contrib[b2];
        *out_loss = -acc * (1.0f / BB);
    }
}

// ---------------- launch -----------------------------------------------------
extern "C" void kernel_launch(void* const* d_in, const int* in_sizes, int n_in,
                              void* d_out, int out_size) {
    const int* x = (const int*)d_in[0];
    const int* mask_idx = (const int*)d_in[1];
    const float* ew = (const float*)d_in[2];
    const float* pw = (const float*)d_in[3];
    float* out = (float*)d_out;

    float* out_loss;
    float* out_sel;
    if (out_size == BB * DD) { out_sel = out; out_loss = nullptr; }
    else if (out_size == 1)  { out_sel = nullptr; out_loss = out; }
    else                     { out_loss = out; out_sel = out + 1; }

    ew_pass_kernel<<<(MM + 1 + 7) / 8, 256>>>(ew);
    pw_pass_kernel<<<LL / 8, 256>>>(pw, mask_idx);
    wsum_kernel<<<dim3(NCHUNK, BB), 128>>>(x, mask_idx, ew);
    reduce_sel_kernel<<<dim3(8, BB), 256>>>(out_sel);
    inner_kernel<<<G_INNER, 256>>>(ew);
    finalize_kernel<<<1, 512>>>(x, mask_idx, ew, out_loss);
}